// round 6
// baseline (speedup 1.0000x reference)
#include <cuda_runtime.h>

#define BATCH 4096
#define TT    512
#define IN    20
#define HID   51
#define NG    204            // 4*HID
#define SPB   16
#define NBLK  (BATCH / SPB)  // 256
#define NTHR  256

// float offsets in dynamic smem
#define OFF_W   0                       // w_t[71][204]: rows 0..50 = W_hh1^T, 51..70 = W_ih1^T
#define OFF_GT  (71 * NG)               // gates [204][20]  (pitch 20)
#define OFF_H   (OFF_GT + NG * 20)      // h [51][16]
#define OFF_XB  (OFF_H + HID * 16)      // xbuf [2][20][16]
#define OFF_W2  (OFF_XB + 2 * IN * 16)  // W_ih2 [4*51]
#define SMEM_FLOATS (OFF_W2 + NG)
#define SMEM_BYTES  (SMEM_FLOATS * 4)   // ~81.7 KB -> 2 CTAs/SM

typedef unsigned long long ull;

__device__ __forceinline__ ull pack2(float v) {
    ull r; asm("mov.b64 %0, {%1, %1};" : "=l"(r) : "f"(v)); return r;
}
__device__ __forceinline__ ull fma2(ull a, ull b, ull c) {
    ull d; asm("fma.rn.f32x2 %0, %1, %2, %3;" : "=l"(d) : "l"(a), "l"(b), "l"(c)); return d;
}
__device__ __forceinline__ float fsig(float x)  { return __fdividef(1.0f, 1.0f + __expf(-x)); }
__device__ __forceinline__ float ftanh_(float x){ return 1.0f - __fdividef(2.0f, __expf(2.0f * x) + 1.0f); }

__global__ __launch_bounds__(NTHR, 2) void lstm_v6_kernel(
    const float* __restrict__ x,
    const float* __restrict__ W_ih1, const float* __restrict__ W_hh1,
    const float* __restrict__ b_ih1, const float* __restrict__ b_hh1,
    const float* __restrict__ W_ih2, const float* __restrict__ W_hh2,
    const float* __restrict__ b_ih2, const float* __restrict__ b_hh2,
    const float* __restrict__ W_mu,  const float* __restrict__ b_mu,
    const float* __restrict__ W_lv,  const float* __restrict__ b_lv,
    float* __restrict__ out)
{
    extern __shared__ float sm[];
    const int tid = threadIdx.x;
    const int b16 = blockIdx.x * SPB;

    // ---------------- init ----------------
    for (int i = tid; i < NG * HID; i += NTHR) {          // W_hh1^T
        int g = i / HID, k = i % HID;
        sm[OFF_W + k * NG + g] = W_hh1[i];
    }
    for (int i = tid; i < NG * IN; i += NTHR) {           // W_ih1^T
        int g = i / IN, j = i % IN;
        sm[OFF_W + (HID + j) * NG + g] = W_ih1[i];
    }
    if (tid < NG) {
        sm[OFF_W2 + tid] = W_ih2[tid];                    // [4][51]
        #pragma unroll
        for (int j = 0; j < 4; j++) sm[OFF_H + tid + NG * j] = 0.f;   // zero h (816)
    }
    if (tid >= NG && tid < NG + SPB) {                    // x(0) -> XB[0], x(1) -> XB[1]
        int s = tid - NG;
        #pragma unroll
        for (int tt = 0; tt < 2; tt++) {
            const float4* xp = reinterpret_cast<const float4*>(
                &x[((size_t)(b16 + s) * TT + tt) * IN]);
            float* xb = &sm[OFF_XB + tt * (IN * 16)];
            #pragma unroll
            for (int q = 0; q < 5; q++) {
                float4 v = xp[q];
                xb[(4*q+0)*16 + s] = v.x; xb[(4*q+1)*16 + s] = v.y;
                xb[(4*q+2)*16 + s] = v.z; xb[(4*q+3)*16 + s] = v.w;
            }
        }
    }

    const int q4  = (tid >> 2) << 2;   // gate quad base (act threads)
    const int sh4 = (tid & 3) << 2;    // seq quad base

    // per-thread packed biases for the 4 gates of this quad
    ull bp[4];
    if (tid < NG) {
        #pragma unroll
        for (int i = 0; i < 4; i++)
            bp[i] = pack2(b_ih1[q4 + i] + b_hh1[q4 + i]);
    }
    float c1[4] = {0.f, 0.f, 0.f, 0.f};

    // layer-2 threads: 224..239 (one per seq)
    const int l2s = tid - 224;
    float c2 = 0.f, h2 = 0.f, sum_h2 = 0.f;
    float l2b[4], l2w[4];
    if (tid >= 224 && l2s < SPB) {
        #pragma unroll
        for (int g = 0; g < 4; g++) { l2b[g] = b_ih2[g] + b_hh2[g]; l2w[g] = W_hh2[g]; }
    }
    __syncthreads();

    // gx(0) in registers: gxa[2i],gxa[2i+1] = gate q4+i, seqs sh4..sh4+3
    ull gxa[8];
    if (tid < NG) {
        #pragma unroll
        for (int i = 0; i < 4; i++) { gxa[2*i] = bp[i]; gxa[2*i+1] = bp[i]; }
        #pragma unroll
        for (int k = 0; k < IN; k++) {
            float4 w = *reinterpret_cast<const float4*>(&sm[OFF_W + (HID + k) * NG + q4]);
            ulonglong2 xv = *reinterpret_cast<const ulonglong2*>(&sm[OFF_XB + k * 16 + sh4]);
            gxa[0] = fma2(pack2(w.x), xv.x, gxa[0]); gxa[1] = fma2(pack2(w.x), xv.y, gxa[1]);
            gxa[2] = fma2(pack2(w.y), xv.x, gxa[2]); gxa[3] = fma2(pack2(w.y), xv.y, gxa[3]);
            gxa[4] = fma2(pack2(w.z), xv.x, gxa[4]); gxa[5] = fma2(pack2(w.z), xv.y, gxa[5]);
            gxa[6] = fma2(pack2(w.w), xv.x, gxa[6]); gxa[7] = fma2(pack2(w.w), xv.y, gxa[7]);
        }
    }

    float4 xr[5];

    #pragma unroll 1
    for (int t = 0; t < TT; t++) {
        // ============ phase 0 ============
        if (tid < NG) {
            // gates(t) = gx(t) + W_hh * h(t-1):  4 gates x 4 seqs, 2 LDS / 8 FFMA2
            ull a0=gxa[0],a1=gxa[1],a2=gxa[2],a3=gxa[3],a4=gxa[4],a5=gxa[5],a6=gxa[6],a7=gxa[7];
            #pragma unroll
            for (int k = 0; k < HID; k++) {
                float4 w = *reinterpret_cast<const float4*>(&sm[OFF_W + k * NG + q4]);
                ulonglong2 hv = *reinterpret_cast<const ulonglong2*>(&sm[OFF_H + k * 16 + sh4]);
                a0 = fma2(pack2(w.x), hv.x, a0); a1 = fma2(pack2(w.x), hv.y, a1);
                a2 = fma2(pack2(w.y), hv.x, a2); a3 = fma2(pack2(w.y), hv.y, a3);
                a4 = fma2(pack2(w.z), hv.x, a4); a5 = fma2(pack2(w.z), hv.y, a5);
                a6 = fma2(pack2(w.w), hv.x, a6); a7 = fma2(pack2(w.w), hv.y, a7);
            }
            *reinterpret_cast<ulonglong2*>(&sm[OFF_GT + (q4+0)*20 + sh4]) = make_ulonglong2(a0, a1);
            *reinterpret_cast<ulonglong2*>(&sm[OFF_GT + (q4+1)*20 + sh4]) = make_ulonglong2(a2, a3);
            *reinterpret_cast<ulonglong2*>(&sm[OFF_GT + (q4+2)*20 + sh4]) = make_ulonglong2(a4, a5);
            *reinterpret_cast<ulonglong2*>(&sm[OFF_GT + (q4+3)*20 + sh4]) = make_ulonglong2(a6, a7);
        } else if (tid < NG + SPB) {
            if (t + 2 < TT) {                       // prefetch x(t+2) to regs
                int s = tid - NG;
                const float4* xp = reinterpret_cast<const float4*>(
                    &x[((size_t)(b16 + s) * TT + t + 2) * IN]);
                #pragma unroll
                for (int q = 0; q < 5; q++) xr[q] = xp[q];
            }
        } else if (tid >= 224 && l2s < SPB && t > 0) {
            // layer 2 consumes h(t-1)
            float zi = 0.f, zf = 0.f, zg = 0.f, zo = 0.f;
            #pragma unroll
            for (int k = 0; k < HID; k++) {
                float hv = sm[OFF_H + k * 16 + l2s];
                zi += sm[OFF_W2 +         k] * hv;
                zf += sm[OFF_W2 + HID   + k] * hv;
                zg += sm[OFF_W2 + 2*HID + k] * hv;
                zo += sm[OFF_W2 + 3*HID + k] * hv;
            }
            float i2 = fsig  (zi + l2b[0] + l2w[0] * h2);
            float f2 = fsig  (zf + l2b[1] + l2w[1] * h2);
            float g2v= ftanh_(zg + l2b[2] + l2w[2] * h2);
            float o2 = fsig  (zo + l2b[3] + l2w[3] * h2);
            c2 = f2 * c2 + i2 * g2v;
            h2 = o2 * ftanh_(c2);
            sum_h2 += h2;
        }
        __syncthreads();

        // ============ phase 1 ============
        if (tid < NG) {
            // gx(t+1) from XB[(t+1)&1]  (fma pipe; overlaps MUFU across warps)
            if (t + 1 < TT) {
                const float* xb = &sm[OFF_XB + ((t + 1) & 1) * (IN * 16)];
                #pragma unroll
                for (int i = 0; i < 4; i++) { gxa[2*i] = bp[i]; gxa[2*i+1] = bp[i]; }
                #pragma unroll
                for (int k = 0; k < IN; k++) {
                    float4 w = *reinterpret_cast<const float4*>(&sm[OFF_W + (HID + k) * NG + q4]);
                    ulonglong2 xv = *reinterpret_cast<const ulonglong2*>(&xb[k * 16 + sh4]);
                    gxa[0] = fma2(pack2(w.x), xv.x, gxa[0]); gxa[1] = fma2(pack2(w.x), xv.y, gxa[1]);
                    gxa[2] = fma2(pack2(w.y), xv.x, gxa[2]); gxa[3] = fma2(pack2(w.y), xv.y, gxa[3]);
                    gxa[4] = fma2(pack2(w.z), xv.x, gxa[4]); gxa[5] = fma2(pack2(w.z), xv.y, gxa[5]);
                    gxa[6] = fma2(pack2(w.w), xv.x, gxa[6]); gxa[7] = fma2(pack2(w.w), xv.y, gxa[7]);
                }
            }
            // activations for 4 cells (MUFU)
            #pragma unroll
            for (int j = 0; j < 4; j++) {
                int cell = tid + NG * j;
                int u = cell >> 4, s = cell & 15;
                float gi = sm[OFF_GT + (u)         * 20 + s];
                float gf = sm[OFF_GT + (HID + u)   * 20 + s];
                float gg = sm[OFF_GT + (2*HID + u) * 20 + s];
                float go = sm[OFF_GT + (3*HID + u) * 20 + s];
                float c  = fsig(gf) * c1[j] + fsig(gi) * ftanh_(gg);
                c1[j] = c;
                sm[OFF_H + u * 16 + s] = fsig(go) * ftanh_(c);
            }
        } else if (tid < NG + SPB) {
            if (t + 2 < TT) {                        // x(t+2) -> XB[t&1]
                int s = tid - NG;
                float* xb = &sm[OFF_XB + (t & 1) * (IN * 16)];
                #pragma unroll
                for (int q = 0; q < 5; q++) {
                    xb[(4*q+0)*16 + s] = xr[q].x; xb[(4*q+1)*16 + s] = xr[q].y;
                    xb[(4*q+2)*16 + s] = xr[q].z; xb[(4*q+3)*16 + s] = xr[q].w;
                }
            }
        }
        __syncthreads();
    }

    // ---------- final layer-2 step (h(T-1)) + epilogue ----------
    if (tid >= 224 && l2s < SPB) {
        float zi = 0.f, zf = 0.f, zg = 0.f, zo = 0.f;
        #pragma unroll
        for (int k = 0; k < HID; k++) {
            float hv = sm[OFF_H + k * 16 + l2s];
            zi += sm[OFF_W2 +         k] * hv;
            zf += sm[OFF_W2 + HID   + k] * hv;
            zg += sm[OFF_W2 + 2*HID + k] * hv;
            zo += sm[OFF_W2 + 3*HID + k] * hv;
        }
        float i2 = fsig  (zi + l2b[0] + l2w[0] * h2);
        float f2 = fsig  (zf + l2b[1] + l2w[1] * h2);
        float g2v= ftanh_(zg + l2b[2] + l2w[2] * h2);
        float o2 = fsig  (zo + l2b[3] + l2w[3] * h2);
        c2 = f2 * c2 + i2 * g2v;
        h2 = o2 * ftanh_(c2);
        sum_h2 += h2;

        float agg = sum_h2 * (1.0f / TT);
        float mu  = W_mu[0] * agg + b_mu[0];
        float lv  = W_lv[0] * agg + b_lv[0];
        float sg  = __expf(0.5f * lv);
        int b = b16 + l2s;
        out[b]           = mu - 1.96f * sg;
        out[BATCH + b]   = mu;
        out[2*BATCH + b] = mu + 1.96f * sg;
        out[3*BATCH + b] = lv;
    }
}

extern "C" void kernel_launch(void* const* d_in, const int* in_sizes, int n_in,
                              void* d_out, int out_size) {
    const float* x     = (const float*)d_in[0];
    const float* W_ih1 = (const float*)d_in[1];
    const float* W_hh1 = (const float*)d_in[2];
    const float* b_ih1 = (const float*)d_in[3];
    const float* b_hh1 = (const float*)d_in[4];
    const float* W_ih2 = (const float*)d_in[5];
    const float* W_hh2 = (const float*)d_in[6];
    const float* b_ih2 = (const float*)d_in[7];
    const float* b_hh2 = (const float*)d_in[8];
    const float* W_mu  = (const float*)d_in[9];
    const float* b_mu  = (const float*)d_in[10];
    const float* W_lv  = (const float*)d_in[11];
    const float* b_lv  = (const float*)d_in[12];
    float* out = (float*)d_out;

    cudaFuncSetAttribute(lstm_v6_kernel,
                         cudaFuncAttributeMaxDynamicSharedMemorySize, SMEM_BYTES);
    lstm_v6_kernel<<<NBLK, NTHR, SMEM_BYTES>>>(x, W_ih1, W_hh1, b_ih1, b_hh1,
                                               W_ih2, W_hh2, b_ih2, b_hh2,
                                               W_mu, b_mu, W_lv, b_lv, out);
}